// round 8
// baseline (speedup 1.0000x reference)
#include <cuda_runtime.h>
#include <cuda_bf16.h>

// NonLocalAttention: B=8, C=256, Ci=128, H=W=64, N=4096, M=1024
#define BB 8
#define CC 256
#define CI 128
#define WW 64
#define NN 4096
#define MM 1024

// fp32 intermediates
__device__ float g_phif[(size_t)BB * NN * CI];
__device__ float g_gf  [(size_t)BB * NN * CI];
__device__ float g_y   [(size_t)BB * NN * CI];
// pre-split bf16 hi/lo packed intermediates
__device__ unsigned g_qH  [(size_t)BB * NN * 64];     // Q  [b][n][kpair]
__device__ unsigned g_qL  [(size_t)BB * NN * 64];
__device__ unsigned g_kH  [(size_t)BB * MM * 64];     // K  [b][m][kpair]
__device__ unsigned g_kL  [(size_t)BB * MM * 64];
__device__ unsigned g_vTH [(size_t)BB * CI * (MM/2)]; // V^T [b][ci][mpair]
__device__ unsigned g_vTL [(size_t)BB * CI * (MM/2)];

// ---------------------------------------------------------------------------
// helpers
// ---------------------------------------------------------------------------
__device__ __forceinline__ void pack2(unsigned& H, unsigned& L, float x0, float x1) {
    float h0 = __bfloat162float(__float2bfloat16_rn(x0));
    float h1 = __bfloat162float(__float2bfloat16_rn(x1));
    __nv_bfloat162 hh = __floats2bfloat162_rn(h0, h1);
    __nv_bfloat162 ll = __floats2bfloat162_rn(x0 - h0, x1 - h1);
    H = *(unsigned*)&hh;
    L = *(unsigned*)&ll;
}
__device__ __forceinline__ void mma16(float* c, unsigned a0, unsigned a1,
                                      unsigned a2, unsigned a3,
                                      unsigned b0, unsigned b1) {
    asm volatile(
        "mma.sync.aligned.m16n8k16.row.col.f32.bf16.bf16.f32 "
        "{%0,%1,%2,%3},{%4,%5,%6,%7},{%8,%9},{%0,%1,%2,%3};\n"
        : "+f"(c[0]), "+f"(c[1]), "+f"(c[2]), "+f"(c[3])
        : "r"(a0), "r"(a1), "r"(a2), "r"(a3), "r"(b0), "r"(b1));
}
__device__ __forceinline__ void ldsm4(unsigned& d0, unsigned& d1,
                                      unsigned& d2, unsigned& d3, const unsigned* p) {
    unsigned a = (unsigned)__cvta_generic_to_shared((void*)p);
    asm volatile("ldmatrix.sync.aligned.m8n8.x4.shared.b16 {%0,%1,%2,%3}, [%4];"
        : "=r"(d0), "=r"(d1), "=r"(d2), "=r"(d3) : "r"(a));
}

// ---------------------------------------------------------------------------
// Kernel 1: 3-way 1x1 conv. Block = 128n, x staged ONCE (full K), loop 6 j-tiles.
// 512 threads, 16 warps = 8 n-stripes x 2 j-halves. bf16x3.
// ---------------------------------------------------------------------------
#define XP 132
#define PROJ_SMEM_WORDS (2*128*XP + 2*64*XP)
#define PROJ_SMEM_BYTES (PROJ_SMEM_WORDS * 4)

__global__ __launch_bounds__(512) void proj3_tc(
    const float* __restrict__ x,
    const float* __restrict__ w_t, const float* __restrict__ b_t,
    const float* __restrict__ w_p, const float* __restrict__ b_p,
    const float* __restrict__ w_g, const float* __restrict__ b_g)
{
    extern __shared__ unsigned sm[];
    unsigned* Xh = sm;                 // [128n][128kp] pitch 132
    unsigned* Xl = Xh + 128 * XP;
    unsigned* Wh = Xl + 128 * XP;      // [64j][128kp] pitch 132
    unsigned* Wl = Wh + 64 * XP;

    const int b  = blockIdx.y;
    const int n0 = blockIdx.x * 128;
    const int tid  = threadIdx.x;
    const int lane = tid & 31, warp = tid >> 5;
    const int gid  = lane >> 2, t4 = lane & 3;
    const int l16  = lane & 15, lh = lane >> 4;
    const int mw   = (warp >> 1) * 16;      // n stripe
    const int nwj  = (warp & 1) * 32;       // j half

    // stage x once: [n][kpair], transpose from [c][n]
    {
        int n   = (tid >> 2) & 127;
        int kpb = tid & 3;
        const float* xb = x + (size_t)b * CC * NN + n0 + n;
        #pragma unroll
        for (int i = 0; i < 32; i++) {
            int kp = kpb + i * 4;
            float v0 = xb[(size_t)(2 * kp) * NN];
            float v1 = xb[(size_t)(2 * kp + 1) * NN];
            unsigned H, L; pack2(H, L, v0, v1);
            Xh[n * XP + kp] = H;
            Xl[n * XP + kp] = L;
        }
    }

    for (int jg = 0; jg < 6; jg++) {
        const float* w;  const float* bias;  float* dstf = 0;  bool is_theta = false;
        if (jg < 2)      { w = w_t; bias = b_t; is_theta = true; }
        else if (jg < 4) { w = w_p; bias = b_p; dstf = g_phif; }
        else             { w = w_g; bias = b_g; dstf = g_gf;  }
        const int cib = (jg & 1) * 64;

        __syncthreads();   // x-stage done (iter0) / prior mma reads of W done
        #pragma unroll
        for (int it = 0; it < 8; it++) {
            int j = tid + it * 512;
            int r = j >> 6, k4 = j & 63;
            float4 v = *(const float4*)&w[(size_t)(cib + r) * CC + k4 * 4];
            unsigned h0, l0, h1, l1;
            pack2(h0, l0, v.x, v.y);
            pack2(h1, l1, v.z, v.w);
            *(uint2*)&Wh[r * XP + k4 * 2] = make_uint2(h0, h1);
            *(uint2*)&Wl[r * XP + k4 * 2] = make_uint2(l0, l1);
        }
        __syncthreads();

        float acc[4][4] = {};
        #pragma unroll
        for (int ks = 0; ks < 16; ks++) {
            unsigned ah0, ah1, ah2, ah3, al0, al1, al2, al3;
            ldsm4(ah0, ah1, ah2, ah3, &Xh[(mw + l16) * XP + ks * 8 + lh * 4]);
            ldsm4(al0, al1, al2, al3, &Xl[(mw + l16) * XP + ks * 8 + lh * 4]);
            unsigned beh0, beh1, beh2, beh3, boh0, boh1, boh2, boh3;
            unsigned bel0, bel1, bel2, bel3, bol0, bol1, bol2, bol3;
            ldsm4(beh0, beh1, beh2, beh3, &Wh[(nwj + l16) * XP + ks * 8 + lh * 4]);
            ldsm4(boh0, boh1, boh2, boh3, &Wh[(nwj + 16 + l16) * XP + ks * 8 + lh * 4]);
            ldsm4(bel0, bel1, bel2, bel3, &Wl[(nwj + l16) * XP + ks * 8 + lh * 4]);
            ldsm4(bol0, bol1, bol2, bol3, &Wl[(nwj + 16 + l16) * XP + ks * 8 + lh * 4]);
            mma16(acc[0], ah0, ah1, ah2, ah3, beh0, beh2);
            mma16(acc[1], ah0, ah1, ah2, ah3, beh1, beh3);
            mma16(acc[2], ah0, ah1, ah2, ah3, boh0, boh2);
            mma16(acc[3], ah0, ah1, ah2, ah3, boh1, boh3);
            mma16(acc[0], ah0, ah1, ah2, ah3, bel0, bel2);
            mma16(acc[1], ah0, ah1, ah2, ah3, bel1, bel3);
            mma16(acc[2], ah0, ah1, ah2, ah3, bol0, bol2);
            mma16(acc[3], ah0, ah1, ah2, ah3, bol1, bol3);
            mma16(acc[0], al0, al1, al2, al3, beh0, beh2);
            mma16(acc[1], al0, al1, al2, al3, beh1, beh3);
            mma16(acc[2], al0, al1, al2, al3, boh0, boh2);
            mma16(acc[3], al0, al1, al2, al3, boh1, boh3);
        }

        const size_t base = (size_t)b * NN + n0;
        #pragma unroll
        for (int nt = 0; nt < 4; nt++) {
            int col = cib + nwj + nt * 8 + 2 * t4;
            float bb0 = bias[col], bb1 = bias[col + 1];
            int r0 = mw + gid;
            float2 v0 = {acc[nt][0] + bb0, acc[nt][1] + bb1};
            float2 v1 = {acc[nt][2] + bb0, acc[nt][3] + bb1};
            if (is_theta) {
                int kw = col >> 1;
                unsigned H, L;
                pack2(H, L, v0.x, v0.y);
                g_qH[(base + r0) * 64 + kw] = H;
                g_qL[(base + r0) * 64 + kw] = L;
                pack2(H, L, v1.x, v1.y);
                g_qH[(base + r0 + 8) * 64 + kw] = H;
                g_qL[(base + r0 + 8) * 64 + kw] = L;
            } else {
                *(float2*)&dstf[(base + r0) * CI + col]     = v0;
                *(float2*)&dstf[(base + r0 + 8) * CI + col] = v1;
            }
        }
    }
}

// ---------------------------------------------------------------------------
// Kernel 2a: pool phi -> packed bf16 hi/lo [b][m][kpair]
// ---------------------------------------------------------------------------
__global__ __launch_bounds__(256) void pool_phi_kernel()
{
    int idx = blockIdx.x * 256 + threadIdx.x;
    int c4 = (idx & 31) * 4;
    int m  = (idx >> 5) & (MM - 1);
    int b  = idx >> 15;
    int hp = m >> 5, wp = m & 31;
    int n00 = (hp * 2) * WW + wp * 2;
    size_t base = ((size_t)b * NN + n00) * CI + c4;

    float4 a0 = *(const float4*)&g_phif[base];
    float4 a1 = *(const float4*)&g_phif[base + CI];
    float4 a2 = *(const float4*)&g_phif[base + (size_t)WW * CI];
    float4 a3 = *(const float4*)&g_phif[base + (size_t)WW * CI + CI];
    float4 r;
    r.x = fmaxf(fmaxf(a0.x, a1.x), fmaxf(a2.x, a3.x));
    r.y = fmaxf(fmaxf(a0.y, a1.y), fmaxf(a2.y, a3.y));
    r.z = fmaxf(fmaxf(a0.z, a1.z), fmaxf(a2.z, a3.z));
    r.w = fmaxf(fmaxf(a0.w, a1.w), fmaxf(a2.w, a3.w));

    unsigned h0, l0, h1, l1;
    pack2(h0, l0, r.x, r.y);
    pack2(h1, l1, r.z, r.w);
    size_t dst = ((size_t)b * MM + m) * 64 + (c4 >> 1);
    *(uint2*)&g_kH[dst] = make_uint2(h0, h1);
    *(uint2*)&g_kL[dst] = make_uint2(l0, l1);
}

// ---------------------------------------------------------------------------
// Kernel 2b: pool g + transpose -> V^T packed along m-pairs [b][ci][mpair]
// ---------------------------------------------------------------------------
__global__ __launch_bounds__(256) void pool_vT_kernel()
{
    int idx = blockIdx.x * 256 + threadIdx.x;
    int ci = idx & 127;
    int mp = (idx >> 7) & 511;
    int b  = idx >> 16;

    float v[2];
    #pragma unroll
    for (int j = 0; j < 2; j++) {
        int m = 2 * mp + j;
        int hp = m >> 5, wp = m & 31;
        int n00 = (hp * 2) * WW + wp * 2;
        size_t base = ((size_t)b * NN + n00) * CI + ci;
        float a0 = g_gf[base];
        float a1 = g_gf[base + CI];
        float a2 = g_gf[base + (size_t)WW * CI];
        float a3 = g_gf[base + (size_t)WW * CI + CI];
        v[j] = fmaxf(fmaxf(a0, a1), fmaxf(a2, a3));
    }
    unsigned H, L; pack2(H, L, v[0], v[1]);
    size_t dst = ((size_t)b * CI + ci) * (MM / 2) + mp;
    g_vTH[dst] = H;
    g_vTL[dst] = L;
}

// ---------------------------------------------------------------------------
// Kernel 3: flash attention, 512 threads (16 warps = 8 q-stripes x 2 halves).
// Warp: S[16q,32m] + O[16q,64ci]. Softmax partials via smem; P via smem.
// ---------------------------------------------------------------------------
#define ATTN_WORDS (2*128*68 + 2*64*68 + 2*128*36 + 2*128*36 + 512)
#define ATTN_SMEM_BYTES (ATTN_WORDS * 4)

__global__ __launch_bounds__(512) void attn_tc()
{
    extern __shared__ unsigned smu[];
    unsigned* QhW = smu;                 // [128q][kw] pitch 68
    unsigned* QlW = QhW + 128 * 68;
    unsigned* KhW = QlW + 128 * 68;      // [64m][kw] pitch 68
    unsigned* KlW = KhW + 64 * 68;
    unsigned* VtH = KlW + 64 * 68;       // [128ci][mp] pitch 36
    unsigned* VtL = VtH + 128 * 36;
    unsigned* PsH = VtL + 128 * 36;      // [128q][mp] pitch 36
    unsigned* PsL = PsH + 128 * 36;
    float*    Pmax = (float*)(PsL + 128 * 36);   // [128][2]
    float*    Psum = Pmax + 256;                  // [128][2]

    const int b   = blockIdx.y;
    const int n0g = blockIdx.x * 128;
    const int tid  = threadIdx.x;
    const int lane = tid & 31, warp = tid >> 5;
    const int gid  = lane >> 2, t4 = lane & 3;
    const int l16  = lane & 15, lh = lane >> 4;
    const int qs   = warp >> 1, h = warp & 1;
    const int qw0  = qs * 16;

    // stage Q once
    const unsigned* QgH = g_qH + ((size_t)b * NN + n0g) * 64;
    const unsigned* QgL = g_qL + ((size_t)b * NN + n0g) * 64;
    #pragma unroll
    for (int it = 0; it < 4; it++) {
        int j = tid + it * 512;
        int q = j >> 4, sg = (j & 15) * 4;
        *(uint4*)&QhW[q * 68 + sg] = *(const uint4*)&QgH[q * 64 + sg];
        *(uint4*)&QlW[q * 68 + sg] = *(const uint4*)&QgL[q * 64 + sg];
    }

    float o[8][4];
    #pragma unroll
    for (int i = 0; i < 8; i++)
        #pragma unroll
        for (int jj = 0; jj < 4; jj++) o[i][jj] = 0.f;
    float m_lo = -1e30f, m_hi = -1e30f, l_lo = 0.f, l_hi = 0.f;

    for (int m0 = 0; m0 < MM; m0 += 64) {
        __syncthreads();     // all PV reads of prior tile done; Q-stage (iter0)
        const unsigned* KgH = g_kH + ((size_t)b * MM + m0) * 64;
        const unsigned* KgL = g_kL + ((size_t)b * MM + m0) * 64;
        const unsigned* VgH = g_vTH + (size_t)b * CI * (MM/2) + (m0 >> 1);
        const unsigned* VgL = g_vTL + (size_t)b * CI * (MM/2) + (m0 >> 1);
        #pragma unroll
        for (int it = 0; it < 2; it++) {
            int j = tid + it * 512;
            int m = j >> 4, sg = (j & 15) * 4;
            *(uint4*)&KhW[m * 68 + sg] = *(const uint4*)&KgH[m * 64 + sg];
            *(uint4*)&KlW[m * 68 + sg] = *(const uint4*)&KgL[m * 64 + sg];
            int ci = j >> 3, sv = (j & 7) * 4;
            *(uint4*)&VtH[ci * 36 + sv] = *(const uint4*)&VgH[(size_t)ci * (MM/2) + sv];
            *(uint4*)&VtL[ci * 36 + sv] = *(const uint4*)&VgL[(size_t)ci * (MM/2) + sv];
        }
        __syncthreads();

        // S = Q K^T on this warp's 32m half
        float s[4][4];
        #pragma unroll
        for (int nt = 0; nt < 4; nt++)
            #pragma unroll
            for (int jj = 0; jj < 4; jj++) s[nt][jj] = 0.f;

        #pragma unroll
        for (int ks = 0; ks < 8; ks++) {
            unsigned ah0, ah1, ah2, ah3, al0, al1, al2, al3;
            ldsm4(ah0, ah1, ah2, ah3, &QhW[(qw0 + l16) * 68 + ks * 8 + lh * 4]);
            ldsm4(al0, al1, al2, al3, &QlW[(qw0 + l16) * 68 + ks * 8 + lh * 4]);
            unsigned beh0, beh1, beh2, beh3, boh0, boh1, boh2, boh3;
            unsigned bel0, bel1, bel2, bel3, bol0, bol1, bol2, bol3;
            ldsm4(beh0, beh1, beh2, beh3, &KhW[(h * 32 + l16) * 68 + ks * 8 + lh * 4]);
            ldsm4(boh0, boh1, boh2, boh3, &KhW[(h * 32 + 16 + l16) * 68 + ks * 8 + lh * 4]);
            ldsm4(bel0, bel1, bel2, bel3, &KlW[(h * 32 + l16) * 68 + ks * 8 + lh * 4]);
            ldsm4(bol0, bol1, bol2, bol3, &KlW[(h * 32 + 16 + l16) * 68 + ks * 8 + lh * 4]);
            mma16(s[0], ah0, ah1, ah2, ah3, beh0, beh2);
            mma16(s[1], ah0, ah1, ah2, ah3, beh1, beh3);
            mma16(s[2], ah0, ah1, ah2, ah3, boh0, boh2);
            mma16(s[3], ah0, ah1, ah2, ah3, boh1, boh3);
            mma16(s[0], ah0, ah1, ah2, ah3, bel0, bel2);
            mma16(s[1], ah0, ah1, ah2, ah3, bel1, bel3);
            mma16(s[2], ah0, ah1, ah2, ah3, bol0, bol2);
            mma16(s[3], ah0, ah1, ah2, ah3, bol1, bol3);
            mma16(s[0], al0, al1, al2, al3, beh0, beh2);
            mma16(s[1], al0, al1, al2, al3, beh1, beh3);
            mma16(s[2], al0, al1, al2, al3, boh0, boh2);
            mma16(s[3], al0, al1, al2, al3, boh1, boh3);
        }

        // partial row max over this 32m half
        float mx0 = -1e30f, mx1 = -1e30f;
        #pragma unroll
        for (int nt = 0; nt < 4; nt++) {
            mx0 = fmaxf(mx0, fmaxf(s[nt][0], s[nt][1]));
            mx1 = fmaxf(mx1, fmaxf(s[nt][2], s[nt][3]));
        }
        mx0 = fmaxf(mx0, __shfl_xor_sync(0xffffffffu, mx0, 1));
        mx0 = fmaxf(mx0, __shfl_xor_sync(0xffffffffu, mx0, 2));
        mx1 = fmaxf(mx1, __shfl_xor_sync(0xffffffffu, mx1, 1));
        mx1 = fmaxf(mx1, __shfl_xor_sync(0xffffffffu, mx1, 2));
        if (t4 == 0) {
            Pmax[(qw0 + gid) * 2 + h]     = mx0;
            Pmax[(qw0 + gid + 8) * 2 + h] = mx1;
        }
        __syncthreads();
        float mn0 = fmaxf(m_lo, fmaxf(Pmax[(qw0 + gid) * 2],     Pmax[(qw0 + gid) * 2 + 1]));
        float mn1 = fmaxf(m_hi, fmaxf(Pmax[(qw0 + gid + 8) * 2], Pmax[(qw0 + gid + 8) * 2 + 1]));
        float al0 = __expf(m_lo - mn0), al1 = __expf(m_hi - mn1);

        float s0v = 0.f, s1v = 0.f;
        #pragma unroll
        for (int nt = 0; nt < 4; nt++) {
            s[nt][0] = __expf(s[nt][0] - mn0);
            s[nt][1] = __expf(s[nt][1] - mn0);
            s[nt][2] = __expf(s[nt][2] - mn1);
            s[nt][3] = __expf(s[nt][3] - mn1);
            s0v += s[nt][0] + s[nt][1];
            s1v += s[nt][2] + s[nt][3];
            unsigned H, L;
            pack2(H, L, s[nt][0], s[nt][1]);
            PsH[(qw0 + gid) * 36 + h * 16 + nt * 4 + t4] = H;
            PsL[(qw0 + gid) * 36 + h * 16 + nt * 4 + t4] = L;
            pack2(H, L, s[nt][2], s[nt][3]);
            PsH[(qw0 + gid + 8) * 36 + h * 16 + nt * 4 + t4] = H;
            PsL[(qw0 + gid + 8) * 36 + h * 16 + nt * 4 + t4] = L;
        }
        s0v += __shfl_xor_sync(0xffffffffu, s0v, 1);
        s0v += __shfl_xor_sync(0xffffffffu, s0v, 2);
        s1v += __shfl_xor_sync(0xffffffffu, s1v, 1);
        s1v += __shfl_xor_sync(0xffffffffu, s1v, 2);
        if (t4 == 0) {
            Psum[(qw0 + gid) * 2 + h]     = s0v;
            Psum[(qw0 + gid + 8) * 2 + h] = s1v;
        }
        __syncthreads();
        l_lo = l_lo * al0 + Psum[(qw0 + gid) * 2]     + Psum[(qw0 + gid) * 2 + 1];
        l_hi = l_hi * al1 + Psum[(qw0 + gid + 8) * 2] + Psum[(qw0 + gid + 8) * 2 + 1];
        m_lo = mn0;  m_hi = mn1;
        #pragma unroll
        for (int nt = 0; nt < 8; nt++) {
            o[nt][0] *= al0; o[nt][1] *= al0;
            o[nt][2] *= al1; o[nt][3] *= al1;
        }

        // O += P V on this warp's 64ci half (P from smem, full 64m)
        #pragma unroll
        for (int ks2 = 0; ks2 < 4; ks2++) {
            unsigned paH0, paH1, paH2, paH3, paL0, paL1, paL2, paL3;
            ldsm4(paH0, paH1, paH2, paH3, &PsH[(qw0 + l16) * 36 + ks2 * 8 + lh * 4]);
            ldsm4(paL0, paL1, paL2, paL3, &PsL[(qw0 + l16) * 36 + ks2 * 8 + lh * 4]);
            #pragma unroll
            for (int pp = 0; pp < 2; pp++) {
                unsigned veh0, veh1, veh2, veh3, voh0, voh1, voh2, voh3;
                unsigned vel0, vel1, vel2, vel3, vol0, vol1, vol2, vol3;
                ldsm4(veh0, veh1, veh2, veh3, &VtH[(h * 64 + (2*pp)   * 16 + l16) * 36 + ks2 * 8 + lh * 4]);
                ldsm4(voh0, voh1, voh2, voh3, &VtH[(h * 64 + (2*pp+1) * 16 + l16) * 36 + ks2 * 8 + lh * 4]);
                ldsm4(vel0, vel1, vel2, vel3, &VtL[(h * 64 + (2*pp)   * 16 + l16) * 36 + ks2 * 8 + lh * 4]);
                ldsm4(vol0, vol1, vol2, vol3, &VtL[(h * 64 + (2*pp+1) * 16 + l16) * 36 + ks2 * 8 + lh * 4]);
                float* o0 = o[4*pp+0]; float* o1 = o[4*pp+1];
                float* o2 = o[4*pp+2]; float* o3 = o[4*pp+3];
                mma16(o0, paH0, paH1, paH2, paH3, veh0, veh2);
                mma16(o1, paH0, paH1, paH2, paH3, veh1, veh3);
                mma16(o2, paH0, paH1, paH2, paH3, voh0, voh2);
                mma16(o3, paH0, paH1, paH2, paH3, voh1, voh3);
                mma16(o0, paH0, paH1, paH2, paH3, vel0, vel2);
                mma16(o1, paH0, paH1, paH2, paH3, vel1, vel3);
                mma16(o2, paH0, paH1, paH2, paH3, vol0, vol2);
                mma16(o3, paH0, paH1, paH2, paH3, vol1, vol3);
                mma16(o0, paL0, paL1, paL2, paL3, veh0, veh2);
                mma16(o1, paL0, paL1, paL2, paL3, veh1, veh3);
                mma16(o2, paL0, paL1, paL2, paL3, voh0, voh2);
                mma16(o3, paL0, paL1, paL2, paL3, voh1, voh3);
            }
        }
    }

    float i0 = 1.f / l_lo, i1 = 1.f / l_hi;
    float* yb = g_y + ((size_t)b * NN + n0g) * CI;
    #pragma unroll
    for (int nt = 0; nt < 8; nt++) {
        int cc = h * 64 + nt * 8 + 2 * t4;
        float2 w0 = {o[nt][0] * i0, o[nt][1] * i0};
        float2 w1 = {o[nt][2] * i1, o[nt][3] * i1};
        *(float2*)&yb[(size_t)(qw0 + gid) * CI + cc]     = w0;
        *(float2*)&yb[(size_t)(qw0 + gid + 8) * CI + cc] = w1;
    }
}

// ---------------------------------------------------------------------------
// Kernel 4: out conv + bias + residual. Block 64n, y staged once, loop 4 c-tiles.
// ---------------------------------------------------------------------------
#define OUT_SMEM_WORDS (2*64*68 + 2*64*68)
#define OUT_SMEM_BYTES (OUT_SMEM_WORDS * 4)

__global__ __launch_bounds__(256) void out_tc(
    const float* __restrict__ x,
    const float* __restrict__ wo, const float* __restrict__ bo,
    float* __restrict__ out)
{
    extern __shared__ unsigned sm[];
    unsigned* Yh = sm;                 // y  [64n][64kp] pitch 68
    unsigned* Yl = Yh + 64 * 68;
    unsigned* Wh = Yl + 64 * 68;       // wo [64c][64kp] pitch 68
    unsigned* Wl = Wh + 64 * 68;

    const int b  = blockIdx.y;
    const int n0 = blockIdx.x * 64;
    const int tid  = threadIdx.x;
    const int lane = tid & 31, warp = tid >> 5;
    const int gid  = lane >> 2, t4 = lane & 3;
    const int l16  = lane & 15, lh = lane >> 4;
    const int mwc  = (warp >> 1) * 16;     // c stripe
    const int nwn  = (warp & 1) * 32;      // n half

    const float* yb = g_y + ((size_t)b * NN + n0) * CI;
    // stage y once (full 128k): 64 rows x 32 float4 = 2048 items
    #pragma unroll
    for (int it = 0; it < 8; it++) {
        int j = tid + it * 256;
        int r = j >> 5, k4 = j & 31;
        float4 v = *(const float4*)&yb[(size_t)r * CI + k4 * 4];
        unsigned h0, l0, h1, l1;
        pack2(h0, l0, v.x, v.y);
        pack2(h1, l1, v.z, v.w);
        *(uint2*)&Yh[r * 68 + k4 * 2] = make_uint2(h0, h1);
        *(uint2*)&Yl[r * 68 + k4 * 2] = make_uint2(l0, l1);
    }

    for (int ct = 0; ct < 4; ct++) {
        const int c0 = ct * 64;
        __syncthreads();   // y-stage (iter0) / prior W reads
        #pragma unroll
        for (int it = 0; it < 8; it++) {
            int j = tid + it * 256;
            int r = j >> 5, k4 = j & 31;
            float4 a = *(const float4*)&wo[(size_t)(c0 + r) * CI + k4 * 4];
            unsigned h0, l0, h1, l1;
            pack2(h0, l0, a.x, a.y);
            pack2(h1, l1, a.z, a.w);
            *(uint2*)&Wh[r * 68 + k4 * 2] = make_uint2(h0, h1);
            *(uint2*)&Wl[r * 68 + k4 * 2] = make_uint2(l0, l1);
        }
        __syncthreads();

        float acc[4][4] = {};
        #pragma unroll
        for (int ks = 0; ks < 8; ks++) {
            unsigned ah0, ah1, ah2, ah3, al0, al1, al2, al3;
            ldsm4(ah0, ah1, ah2, ah3, &Wh[(mwc + l16) * 68 + ks * 8 + lh * 4]);
            ldsm4(al0, al1, al2, al3, &Wl[(mwc + l16) * 68 + ks * 8 + lh * 4]);
            unsigned beh0, beh1, beh2, beh3, boh0, boh1, boh2, boh3;
            unsigned bel0, bel1, bel2, bel3, bol0, bol1, bol2, bol3;
            ldsm4(beh0, beh1, beh2, beh3, &Yh[(nwn + l16) * 68 + ks * 8 + lh * 4]);
            ldsm4(boh0, boh1, boh2, boh3, &Yh[(nwn + 16 + l16) * 68 + ks * 8 + lh * 4]);
            ldsm4(bel0, bel1, bel2, bel3, &Yl[(nwn + l16) * 68 + ks * 8 + lh * 4]);
            ldsm4(bol0, bol1, bol2, bol3, &Yl[(nwn + 16 + l16) * 68 + ks * 8 + lh * 4]);
            mma16(acc[0], ah0, ah1, ah2, ah3, beh0, beh2);
            mma16(acc[1], ah0, ah1, ah2, ah3, beh1, beh3);
            mma16(acc[2], ah0, ah1, ah2, ah3, boh0, boh2);
            mma16(acc[3], ah0, ah1, ah2, ah3, boh1, boh3);
            mma16(acc[0], ah0, ah1, ah2, ah3, bel0, bel2);
            mma16(acc[1], ah0, ah1, ah2, ah3, bel1, bel3);
            mma16(acc[2], ah0, ah1, ah2, ah3, bol0, bol2);
            mma16(acc[3], ah0, ah1, ah2, ah3, bol1, bol3);
            mma16(acc[0], al0, al1, al2, al3, beh0, beh2);
            mma16(acc[1], al0, al1, al2, al3, beh1, beh3);
            mma16(acc[2], al0, al1, al2, al3, boh0, boh2);
            mma16(acc[3], al0, al1, al2, al3, boh1, boh3);
        }

        #pragma unroll
        for (int nt = 0; nt < 4; nt++) {
            int c = c0 + mwc + gid;
            int n = n0 + nwn + nt * 8 + 2 * t4;
            float bias0 = bo[c], bias1 = bo[c + 8];
            size_t off0 = ((size_t)b * CC + c) * NN + n;
            size_t off1 = ((size_t)b * CC + c + 8) * NN + n;
            float2 x0 = *(const float2*)&x[off0];
            float2 x1 = *(const float2*)&x[off1];
            float2 r0 = {acc[nt][0] + x0.x + bias0, acc[nt][1] + x0.y + bias0};
            float2 r1 = {acc[nt][2] + x1.x + bias1, acc[nt][3] + x1.y + bias1};
            *(float2*)&out[off0] = r0;
            *(float2*)&out[off1] = r1;
        }
    }
}

// ---------------------------------------------------------------------------
extern "C" void kernel_launch(void* const* d_in, const int* in_sizes, int n_in,
                              void* d_out, int out_size)
{
    const float* x  = (const float*)d_in[0];
    const float* wt = (const float*)d_in[1];
    const float* bt = (const float*)d_in[2];
    const float* wp = (const float*)d_in[3];
    const float* bp = (const float*)d_in[4];
    const float* wg = (const float*)d_in[5];
    const float* bg = (const float*)d_in[6];
    const float* wo = (const float*)d_in[7];
    const float* bo = (const float*)d_in[8];
    float* out = (float*)d_out;

    cudaFuncSetAttribute(proj3_tc, cudaFuncAttributeMaxDynamicSharedMemorySize, PROJ_SMEM_BYTES);
    cudaFuncSetAttribute(attn_tc,  cudaFuncAttributeMaxDynamicSharedMemorySize, ATTN_SMEM_BYTES);
    cudaFuncSetAttribute(out_tc,   cudaFuncAttributeMaxDynamicSharedMemorySize, OUT_SMEM_BYTES);

    proj3_tc<<<dim3(NN / 128, BB), 512, PROJ_SMEM_BYTES>>>(x, wt, bt, wp, bp, wg, bg);
    pool_phi_kernel<<<(BB * MM * 32) / 256, 256>>>();
    pool_vT_kernel<<<(BB * 512 * 128) / 256, 256>>>();
    attn_tc<<<dim3(NN / 128, BB), 512, ATTN_SMEM_BYTES>>>();
    out_tc<<<dim3(NN / 64, BB), 256, OUT_SMEM_BYTES>>>(x, wo, bo, out);
}

// round 14
// speedup vs baseline: 1.1135x; 1.1135x over previous
#include <cuda_runtime.h>
#include <cuda_bf16.h>

// NonLocalAttention: B=8, C=256, Ci=128, H=W=64, N=4096, M=1024
#define BB 8
#define CC 256
#define CI 128
#define WW 64
#define NN 4096
#define MM 1024

// fp32 intermediates
__device__ float g_phif[(size_t)BB * NN * CI];
__device__ float g_gf  [(size_t)BB * NN * CI];
__device__ float g_y   [(size_t)BB * NN * CI];
__device__ float g_vp  [(size_t)BB * MM * CI];   // pooled V, tf32-rounded fp32 [b][m][ci]
// pre-split bf16 hi/lo packed intermediates
__device__ unsigned g_qH  [(size_t)BB * NN * 64];     // Q  [b][n][kpair]
__device__ unsigned g_qL  [(size_t)BB * NN * 64];
__device__ unsigned g_kH  [(size_t)BB * MM * 64];     // K  [b][m][kpair]
__device__ unsigned g_kL  [(size_t)BB * MM * 64];

// ---------------------------------------------------------------------------
// helpers
// ---------------------------------------------------------------------------
__device__ __forceinline__ void pack2(unsigned& H, unsigned& L, float x0, float x1) {
    float h0 = __bfloat162float(__float2bfloat16_rn(x0));
    float h1 = __bfloat162float(__float2bfloat16_rn(x1));
    __nv_bfloat162 hh = __floats2bfloat162_rn(h0, h1);
    __nv_bfloat162 ll = __floats2bfloat162_rn(x0 - h0, x1 - h1);
    H = *(unsigned*)&hh;
    L = *(unsigned*)&ll;
}
__device__ __forceinline__ unsigned cvt_tf32(float x) {
    unsigned u;
    asm("cvt.rna.tf32.f32 %0, %1;" : "=r"(u) : "f"(x));
    return u;
}
__device__ __forceinline__ void mma16(float* c, unsigned a0, unsigned a1,
                                      unsigned a2, unsigned a3,
                                      unsigned b0, unsigned b1) {
    asm volatile(
        "mma.sync.aligned.m16n8k16.row.col.f32.bf16.bf16.f32 "
        "{%0,%1,%2,%3},{%4,%5,%6,%7},{%8,%9},{%0,%1,%2,%3};\n"
        : "+f"(c[0]), "+f"(c[1]), "+f"(c[2]), "+f"(c[3])
        : "r"(a0), "r"(a1), "r"(a2), "r"(a3), "r"(b0), "r"(b1));
}
__device__ __forceinline__ void mma8_tf32(float* c, unsigned a0, unsigned a1,
                                          unsigned a2, unsigned a3,
                                          unsigned b0, unsigned b1) {
    asm volatile(
        "mma.sync.aligned.m16n8k8.row.col.f32.tf32.tf32.f32 "
        "{%0,%1,%2,%3},{%4,%5,%6,%7},{%8,%9},{%0,%1,%2,%3};\n"
        : "+f"(c[0]), "+f"(c[1]), "+f"(c[2]), "+f"(c[3])
        : "r"(a0), "r"(a1), "r"(a2), "r"(a3), "r"(b0), "r"(b1));
}
__device__ __forceinline__ void ldsm4(unsigned& d0, unsigned& d1,
                                      unsigned& d2, unsigned& d3, const unsigned* p) {
    unsigned a = (unsigned)__cvta_generic_to_shared((void*)p);
    asm volatile("ldmatrix.sync.aligned.m8n8.x4.shared.b16 {%0,%1,%2,%3}, [%4];"
        : "=r"(d0), "=r"(d1), "=r"(d2), "=r"(d3) : "r"(a));
}

// ---------------------------------------------------------------------------
// Kernel 1: 3-way 1x1 conv. Block = 128n, x staged ONCE (full K), loop 6 j-tiles.
// 512 threads, 16 warps = 8 n-stripes x 2 j-halves. bf16x3.
// ---------------------------------------------------------------------------
#define XP 132
#define PROJ_SMEM_WORDS (2*128*XP + 2*64*XP)
#define PROJ_SMEM_BYTES (PROJ_SMEM_WORDS * 4)

__global__ __launch_bounds__(512) void proj3_tc(
    const float* __restrict__ x,
    const float* __restrict__ w_t, const float* __restrict__ b_t,
    const float* __restrict__ w_p, const float* __restrict__ b_p,
    const float* __restrict__ w_g, const float* __restrict__ b_g)
{
    extern __shared__ unsigned sm[];
    unsigned* Xh = sm;                 // [128n][128kp] pitch 132
    unsigned* Xl = Xh + 128 * XP;
    unsigned* Wh = Xl + 128 * XP;      // [64j][128kp] pitch 132
    unsigned* Wl = Wh + 64 * XP;

    const int b  = blockIdx.y;
    const int n0 = blockIdx.x * 128;
    const int tid  = threadIdx.x;
    const int lane = tid & 31, warp = tid >> 5;
    const int gid  = lane >> 2, t4 = lane & 3;
    const int l16  = lane & 15, lh = lane >> 4;
    const int mw   = (warp >> 1) * 16;      // n stripe
    const int nwj  = (warp & 1) * 32;       // j half

    // stage x once: [n][kpair], transpose from [c][n]
    {
        int n   = (tid >> 2) & 127;
        int kpb = tid & 3;
        const float* xb = x + (size_t)b * CC * NN + n0 + n;
        #pragma unroll
        for (int i = 0; i < 32; i++) {
            int kp = kpb + i * 4;
            float v0 = xb[(size_t)(2 * kp) * NN];
            float v1 = xb[(size_t)(2 * kp + 1) * NN];
            unsigned H, L; pack2(H, L, v0, v1);
            Xh[n * XP + kp] = H;
            Xl[n * XP + kp] = L;
        }
    }

    for (int jg = 0; jg < 6; jg++) {
        const float* w;  const float* bias;  float* dstf = 0;  bool is_theta = false;
        if (jg < 2)      { w = w_t; bias = b_t; is_theta = true; }
        else if (jg < 4) { w = w_p; bias = b_p; dstf = g_phif; }
        else             { w = w_g; bias = b_g; dstf = g_gf;  }
        const int cib = (jg & 1) * 64;

        __syncthreads();   // x-stage done (iter0) / prior mma reads of W done
        #pragma unroll
        for (int it = 0; it < 8; it++) {
            int j = tid + it * 512;
            int r = j >> 6, k4 = j & 63;
            float4 v = *(const float4*)&w[(size_t)(cib + r) * CC + k4 * 4];
            unsigned h0, l0, h1, l1;
            pack2(h0, l0, v.x, v.y);
            pack2(h1, l1, v.z, v.w);
            *(uint2*)&Wh[r * XP + k4 * 2] = make_uint2(h0, h1);
            *(uint2*)&Wl[r * XP + k4 * 2] = make_uint2(l0, l1);
        }
        __syncthreads();

        float acc[4][4] = {};
        #pragma unroll
        for (int ks = 0; ks < 16; ks++) {
            unsigned ah0, ah1, ah2, ah3, al0, al1, al2, al3;
            ldsm4(ah0, ah1, ah2, ah3, &Xh[(mw + l16) * XP + ks * 8 + lh * 4]);
            ldsm4(al0, al1, al2, al3, &Xl[(mw + l16) * XP + ks * 8 + lh * 4]);
            unsigned beh0, beh1, beh2, beh3, boh0, boh1, boh2, boh3;
            unsigned bel0, bel1, bel2, bel3, bol0, bol1, bol2, bol3;
            ldsm4(beh0, beh1, beh2, beh3, &Wh[(nwj + l16) * XP + ks * 8 + lh * 4]);
            ldsm4(boh0, boh1, boh2, boh3, &Wh[(nwj + 16 + l16) * XP + ks * 8 + lh * 4]);
            ldsm4(bel0, bel1, bel2, bel3, &Wl[(nwj + l16) * XP + ks * 8 + lh * 4]);
            ldsm4(bol0, bol1, bol2, bol3, &Wl[(nwj + 16 + l16) * XP + ks * 8 + lh * 4]);
            mma16(acc[0], ah0, ah1, ah2, ah3, beh0, beh2);
            mma16(acc[1], ah0, ah1, ah2, ah3, beh1, beh3);
            mma16(acc[2], ah0, ah1, ah2, ah3, boh0, boh2);
            mma16(acc[3], ah0, ah1, ah2, ah3, boh1, boh3);
            mma16(acc[0], ah0, ah1, ah2, ah3, bel0, bel2);
            mma16(acc[1], ah0, ah1, ah2, ah3, bel1, bel3);
            mma16(acc[2], ah0, ah1, ah2, ah3, bol0, bol2);
            mma16(acc[3], ah0, ah1, ah2, ah3, bol1, bol3);
            mma16(acc[0], al0, al1, al2, al3, beh0, beh2);
            mma16(acc[1], al0, al1, al2, al3, beh1, beh3);
            mma16(acc[2], al0, al1, al2, al3, boh0, boh2);
            mma16(acc[3], al0, al1, al2, al3, boh1, boh3);
        }

        const size_t base = (size_t)b * NN + n0;
        #pragma unroll
        for (int nt = 0; nt < 4; nt++) {
            int col = cib + nwj + nt * 8 + 2 * t4;
            float bb0 = bias[col], bb1 = bias[col + 1];
            int r0 = mw + gid;
            float2 v0 = {acc[nt][0] + bb0, acc[nt][1] + bb1};
            float2 v1 = {acc[nt][2] + bb0, acc[nt][3] + bb1};
            if (is_theta) {
                int kw = col >> 1;
                unsigned H, L;
                pack2(H, L, v0.x, v0.y);
                g_qH[(base + r0) * 64 + kw] = H;
                g_qL[(base + r0) * 64 + kw] = L;
                pack2(H, L, v1.x, v1.y);
                g_qH[(base + r0 + 8) * 64 + kw] = H;
                g_qL[(base + r0 + 8) * 64 + kw] = L;
            } else {
                *(float2*)&dstf[(base + r0) * CI + col]     = v0;
                *(float2*)&dstf[(base + r0 + 8) * CI + col] = v1;
            }
        }
    }
}

// ---------------------------------------------------------------------------
// Kernel 2: pool. phi -> packed bf16 hi/lo K [b][m][kpair];
//           g -> tf32-rounded fp32 V [b][m][ci].
// ---------------------------------------------------------------------------
__global__ __launch_bounds__(256) void pool_kernel()
{
    int idx = blockIdx.x * 256 + threadIdx.x;
    int c4 = (idx & 31) * 4;
    int m  = (idx >> 5) & (MM - 1);
    int b  = idx >> 15;
    int hp = m >> 5, wp = m & 31;
    int n00 = (hp * 2) * WW + wp * 2;
    size_t base = ((size_t)b * NN + n00) * CI + c4;

    // phi -> K packed
    float4 a0 = *(const float4*)&g_phif[base];
    float4 a1 = *(const float4*)&g_phif[base + CI];
    float4 a2 = *(const float4*)&g_phif[base + (size_t)WW * CI];
    float4 a3 = *(const float4*)&g_phif[base + (size_t)WW * CI + CI];
    float4 r;
    r.x = fmaxf(fmaxf(a0.x, a1.x), fmaxf(a2.x, a3.x));
    r.y = fmaxf(fmaxf(a0.y, a1.y), fmaxf(a2.y, a3.y));
    r.z = fmaxf(fmaxf(a0.z, a1.z), fmaxf(a2.z, a3.z));
    r.w = fmaxf(fmaxf(a0.w, a1.w), fmaxf(a2.w, a3.w));
    unsigned h0, l0, h1, l1;
    pack2(h0, l0, r.x, r.y);
    pack2(h1, l1, r.z, r.w);
    size_t dstk = ((size_t)b * MM + m) * 64 + (c4 >> 1);
    *(uint2*)&g_kH[dstk] = make_uint2(h0, h1);
    *(uint2*)&g_kL[dstk] = make_uint2(l0, l1);

    // g -> V tf32-rounded fp32
    a0 = *(const float4*)&g_gf[base];
    a1 = *(const float4*)&g_gf[base + CI];
    a2 = *(const float4*)&g_gf[base + (size_t)WW * CI];
    a3 = *(const float4*)&g_gf[base + (size_t)WW * CI + CI];
    r.x = fmaxf(fmaxf(a0.x, a1.x), fmaxf(a2.x, a3.x));
    r.y = fmaxf(fmaxf(a0.y, a1.y), fmaxf(a2.y, a3.y));
    r.z = fmaxf(fmaxf(a0.z, a1.z), fmaxf(a2.z, a3.z));
    r.w = fmaxf(fmaxf(a0.w, a1.w), fmaxf(a2.w, a3.w));
    float4 vt;
    vt.x = __uint_as_float(cvt_tf32(r.x));
    vt.y = __uint_as_float(cvt_tf32(r.y));
    vt.z = __uint_as_float(cvt_tf32(r.z));
    vt.w = __uint_as_float(cvt_tf32(r.w));
    *(float4*)&g_vp[((size_t)b * MM + m) * CI + c4] = vt;
}

// ---------------------------------------------------------------------------
// Kernel 3: flash attention. 256 thr, warp = 16q x full 64m stripe.
// QK bf16x3 (ldmatrix, S in regs); PV tf32 single-pass via smem P (R4 path).
// ---------------------------------------------------------------------------
#define ATTN_WORDS (2*128*68 + 2*64*68 + 64*136 + 128*68)
#define ATTN_SMEM_BYTES (ATTN_WORDS * 4)

__global__ __launch_bounds__(256, 1) void attn_tc()
{
    extern __shared__ unsigned smu[];
    unsigned* QhW = smu;                 // [q=128][kw] pitch 68
    unsigned* QlW = QhW + 128 * 68;
    unsigned* KhW = QlW + 128 * 68;      // [m=64][kw] pitch 68
    unsigned* KlW = KhW + 64 * 68;
    float*    Vh  = (float*)(KlW + 64 * 68);   // [m=64][ci=128] pitch 136 (tf32)
    float*    Ps  = Vh + 64 * 136;             // [q=128][m=64] pitch 68

    const int b  = blockIdx.y;
    const int n0 = blockIdx.x * 128;
    const int tid  = threadIdx.x;
    const int lane = tid & 31, warp = tid >> 5;
    const int gid  = lane >> 2, t4 = lane & 3;
    const int qw   = warp * 16;
    const int l16  = lane & 15, lh = lane >> 4;

    // stage Q once
    const unsigned* QgH = g_qH + ((size_t)b * NN + n0) * 64;
    const unsigned* QgL = g_qL + ((size_t)b * NN + n0) * 64;
    #pragma unroll
    for (int it = 0; it < 8; it++) {
        int j = tid + it * 256;
        int q = j >> 4, sg = (j & 15) * 4;
        *(uint4*)&QhW[q * 68 + sg] = *(const uint4*)&QgH[q * 64 + sg];
        *(uint4*)&QlW[q * 68 + sg] = *(const uint4*)&QgL[q * 64 + sg];
    }

    float o[16][4];
    #pragma unroll
    for (int i = 0; i < 16; i++)
        #pragma unroll
        for (int jj = 0; jj < 4; jj++) o[i][jj] = 0.f;
    float m_lo = -1e30f, m_hi = -1e30f, l_lo = 0.f, l_hi = 0.f;

    for (int m0 = 0; m0 < MM; m0 += 64) {
        __syncthreads();
        const unsigned* KgH = g_kH + ((size_t)b * MM + m0) * 64;
        const unsigned* KgL = g_kL + ((size_t)b * MM + m0) * 64;
        const float*    Vg  = g_vp + ((size_t)b * MM + m0) * CI;
        #pragma unroll
        for (int it = 0; it < 4; it++) {
            int j = tid + it * 256;
            int m = j >> 4, sg = (j & 15) * 4;
            *(uint4*)&KhW[m * 68 + sg] = *(const uint4*)&KgH[m * 64 + sg];
            *(uint4*)&KlW[m * 68 + sg] = *(const uint4*)&KgL[m * 64 + sg];
        }
        #pragma unroll
        for (int it = 0; it < 8; it++) {
            int j = tid + it * 256;
            int m = j >> 5, sv = (j & 31) * 4;
            *(uint4*)&Vh[m * 136 + sv] = *(const uint4*)&Vg[(size_t)m * CI + sv];
        }
        __syncthreads();

        // S = Q K^T : bf16x3
        float s[8][4];
        #pragma unroll
        for (int nt = 0; nt < 8; nt++)
            #pragma unroll
            for (int jj = 0; jj < 4; jj++) s[nt][jj] = 0.f;

        #pragma unroll
        for (int ks = 0; ks < 8; ks++) {
            unsigned ah0, ah1, ah2, ah3, al0, al1, al2, al3;
            ldsm4(ah0, ah1, ah2, ah3, &QhW[(qw + l16) * 68 + ks * 8 + lh * 4]);
            ldsm4(al0, al1, al2, al3, &QlW[(qw + l16) * 68 + ks * 8 + lh * 4]);
            #pragma unroll
            for (int pp = 0; pp < 2; pp++) {
                unsigned beh0, beh1, beh2, beh3, boh0, boh1, boh2, boh3;
                unsigned bel0, bel1, bel2, bel3, bol0, bol1, bol2, bol3;
                ldsm4(beh0, beh1, beh2, beh3, &KhW[((2*pp)   * 16 + l16) * 68 + ks * 8 + lh * 4]);
                ldsm4(boh0, boh1, boh2, boh3, &KhW[((2*pp+1) * 16 + l16) * 68 + ks * 8 + lh * 4]);
                ldsm4(bel0, bel1, bel2, bel3, &KlW[((2*pp)   * 16 + l16) * 68 + ks * 8 + lh * 4]);
                ldsm4(bol0, bol1, bol2, bol3, &KlW[((2*pp+1) * 16 + l16) * 68 + ks * 8 + lh * 4]);
                float* s0 = s[4*pp+0]; float* s1 = s[4*pp+1];
                float* s2 = s[4*pp+2]; float* s3 = s[4*pp+3];
                mma16(s0, ah0, ah1, ah2, ah3, beh0, beh2);
                mma16(s1, ah0, ah1, ah2, ah3, beh1, beh3);
                mma16(s2, ah0, ah1, ah2, ah3, boh0, boh2);
                mma16(s3, ah0, ah1, ah2, ah3, boh1, boh3);
                mma16(s0, ah0, ah1, ah2, ah3, bel0, bel2);
                mma16(s1, ah0, ah1, ah2, ah3, bel1, bel3);
                mma16(s2, ah0, ah1, ah2, ah3, bol0, bol2);
                mma16(s3, ah0, ah1, ah2, ah3, bol1, bol3);
                mma16(s0, al0, al1, al2, al3, beh0, beh2);
                mma16(s1, al0, al1, al2, al3, beh1, beh3);
                mma16(s2, al0, al1, al2, al3, boh0, boh2);
                mma16(s3, al0, al1, al2, al3, boh1, boh3);
            }
        }

        // online softmax (warp-local rows); p written to smem Ps for PV
        float mx0 = -1e30f, mx1 = -1e30f;
        #pragma unroll
        for (int nt = 0; nt < 8; nt++) {
            mx0 = fmaxf(mx0, fmaxf(s[nt][0], s[nt][1]));
            mx1 = fmaxf(mx1, fmaxf(s[nt][2], s[nt][3]));
        }
        mx0 = fmaxf(mx0, __shfl_xor_sync(0xffffffffu, mx0, 1));
        mx0 = fmaxf(mx0, __shfl_xor_sync(0xffffffffu, mx0, 2));
        mx1 = fmaxf(mx1, __shfl_xor_sync(0xffffffffu, mx1, 1));
        mx1 = fmaxf(mx1, __shfl_xor_sync(0xffffffffu, mx1, 2));
        float mn0 = fmaxf(m_lo, mx0), mn1 = fmaxf(m_hi, mx1);
        float al0 = __expf(m_lo - mn0), al1 = __expf(m_hi - mn1);
        float s0v = 0.f, s1v = 0.f;
        #pragma unroll
        for (int nt = 0; nt < 8; nt++) {
            float p0 = __expf(s[nt][0] - mn0);
            float p1 = __expf(s[nt][1] - mn0);
            float p2 = __expf(s[nt][2] - mn1);
            float p3 = __expf(s[nt][3] - mn1);
            s0v += p0 + p1; s1v += p2 + p3;
            *(float2*)&Ps[(qw + gid) * 68 + nt * 8 + 2 * t4]     = make_float2(p0, p1);
            *(float2*)&Ps[(qw + gid + 8) * 68 + nt * 8 + 2 * t4] = make_float2(p2, p3);
        }
        s0v += __shfl_xor_sync(0xffffffffu, s0v, 1);
        s0v += __shfl_xor_sync(0xffffffffu, s0v, 2);
        s1v += __shfl_xor_sync(0xffffffffu, s1v, 1);
        s1v += __shfl_xor_sync(0xffffffffu, s1v, 2);
        l_lo = l_lo * al0 + s0v; m_lo = mn0;
        l_hi = l_hi * al1 + s1v; m_hi = mn1;
        #pragma unroll
        for (int nt = 0; nt < 16; nt++) {
            o[nt][0] *= al0; o[nt][1] *= al0;
            o[nt][2] *= al1; o[nt][3] *= al1;
        }
        __syncwarp();   // warp-private Ps rows: publish before PV reads

        // O += P V : tf32 single pass (m16n8k8), V fragments scalar from Vh
        #pragma unroll
        for (int ks = 0; ks < 8; ks++) {
            int ko = ks * 8 + t4;
            unsigned ph0 = cvt_tf32(Ps[(qw + gid) * 68 + ko]);
            unsigned ph1 = cvt_tf32(Ps[(qw + gid + 8) * 68 + ko]);
            unsigned ph2 = cvt_tf32(Ps[(qw + gid) * 68 + ko + 4]);
            unsigned ph3 = cvt_tf32(Ps[(qw + gid + 8) * 68 + ko + 4]);
            #pragma unroll
            for (int nt = 0; nt < 16; nt++) {
                int cc = nt * 8 + gid;
                unsigned b0 = __float_as_uint(Vh[ko * 136 + cc]);
                unsigned b1 = __float_as_uint(Vh[(ko + 4) * 136 + cc]);
                mma8_tf32(o[nt], ph0, ph1, ph2, ph3, b0, b1);
            }
        }
    }

    float i0 = 1.f / l_lo, i1 = 1.f / l_hi;
    float* yb = g_y + ((size_t)b * NN + n0) * CI;
    #pragma unroll
    for (int nt = 0; nt < 16; nt++) {
        int cc = nt * 8 + 2 * t4;
        float2 w0 = {o[nt][0] * i0, o[nt][1] * i0};
        float2 w1 = {o[nt][2] * i1, o[nt][3] * i1};
        *(float2*)&yb[(size_t)(qw + gid) * CI + cc]     = w0;
        *(float2*)&yb[(size_t)(qw + gid + 8) * CI + cc] = w1;
    }
}

// ---------------------------------------------------------------------------
// Kernel 4: out conv + bias + residual. Block 64n, y staged once, loop 4 c-tiles.
// ---------------------------------------------------------------------------
#define OUT_SMEM_WORDS (2*64*68 + 2*64*68)
#define OUT_SMEM_BYTES (OUT_SMEM_WORDS * 4)

__global__ __launch_bounds__(256) void out_tc(
    const float* __restrict__ x,
    const float* __restrict__ wo, const float* __restrict__ bo,
    float* __restrict__ out)
{
    extern __shared__ unsigned sm[];
    unsigned* Yh = sm;                 // y  [64n][64kp] pitch 68
    unsigned* Yl = Yh + 64 * 68;
    unsigned* Wh = Yl + 64 * 68;       // wo [64c][64kp] pitch 68
    unsigned* Wl = Wh + 64 * 68;

    const int b  = blockIdx.y;
    const int n0 = blockIdx.x * 64;
    const int tid  = threadIdx.x;
    const int lane = tid & 31, warp = tid >> 5;
    const int gid  = lane >> 2, t4 = lane & 3;
    const int l16  = lane & 15, lh = lane >> 4;
    const int mwc  = (warp >> 1) * 16;     // c stripe
    const int nwn  = (warp & 1) * 32;      // n half

    const float* yb = g_y + ((size_t)b * NN + n0) * CI;
    // stage y once (full 128k): 64 rows x 32 float4
    #pragma unroll
    for (int it = 0; it < 8; it++) {
        int j = tid + it * 256;
        int r = j >> 5, k4 = j & 31;
        float4 v = *(const float4*)&yb[(size_t)r * CI + k4 * 4];
        unsigned h0, l0, h1, l1;
        pack2(h0, l0, v.x, v.y);
        pack2(h1, l1, v.z, v.w);
        *(uint2*)&Yh[r * 68 + k4 * 2] = make_uint2(h0, h1);
        *(uint2*)&Yl[r * 68 + k4 * 2] = make_uint2(l0, l1);
    }

    for (int ct = 0; ct < 4; ct++) {
        const int c0 = ct * 64;
        __syncthreads();
        #pragma unroll
        for (int it = 0; it < 8; it++) {
            int j = tid + it * 256;
            int r = j >> 5, k4 = j & 31;
            float4 a = *(const float4*)&wo[(size_t)(c0 + r) * CI + k4 * 4];
            unsigned h0, l0, h1, l1;
            pack2(h0, l0, a.x, a.y);
            pack2(h1, l1, a.z, a.w);
            *(uint2*)&Wh[r * 68 + k4 * 2] = make_uint2(h0, h1);
            *(uint2*)&Wl[r * 68 + k4 * 2] = make_uint2(l0, l1);
        }
        __syncthreads();

        float acc[4][4] = {};
        #pragma unroll
        for (int ks = 0; ks < 8; ks++) {
            unsigned ah0, ah1, ah2, ah3, al0, al1, al2, al3;
            ldsm4(ah0, ah1, ah2, ah3, &Wh[(mwc + l16) * 68 + ks * 8 + lh * 4]);
            ldsm4(al0, al1, al2, al3, &Wl[(mwc + l16) * 68 + ks * 8 + lh * 4]);
            unsigned beh0, beh1, beh2, beh3, boh0, boh1, boh2, boh3;
            unsigned bel0, bel1, bel2, bel3, bol0, bol1, bol2, bol3;
            ldsm4(beh0, beh1, beh2, beh3, &Yh[(nwn + l16) * 68 + ks * 8 + lh * 4]);
            ldsm4(boh0, boh1, boh2, boh3, &Yh[(nwn + 16 + l16) * 68 + ks * 8 + lh * 4]);
            ldsm4(bel0, bel1, bel2, bel3, &Yl[(nwn + l16) * 68 + ks * 8 + lh * 4]);
            ldsm4(bol0, bol1, bol2, bol3, &Yl[(nwn + 16 + l16) * 68 + ks * 8 + lh * 4]);
            mma16(acc[0], ah0, ah1, ah2, ah3, beh0, beh2);
            mma16(acc[1], ah0, ah1, ah2, ah3, beh1, beh3);
            mma16(acc[2], ah0, ah1, ah2, ah3, boh0, boh2);
            mma16(acc[3], ah0, ah1, ah2, ah3, boh1, boh3);
            mma16(acc[0], ah0, ah1, ah2, ah3, bel0, bel2);
            mma16(acc[1], ah0, ah1, ah2, ah3, bel1, bel3);
            mma16(acc[2], ah0, ah1, ah2, ah3, bol0, bol2);
            mma16(acc[3], ah0, ah1, ah2, ah3, bol1, bol3);
            mma16(acc[0], al0, al1, al2, al3, beh0, beh2);
            mma16(acc[1], al0, al1, al2, al3, beh1, beh3);
            mma16(acc[2], al0, al1, al2, al3, boh0, boh2);
            mma16(acc[3], al0, al1, al2, al3, boh1, boh3);
        }

        #pragma unroll
        for (int nt = 0; nt < 4; nt++) {
            int c = c0 + mwc + gid;
            int n = n0 + nwn + nt * 8 + 2 * t4;
            float bias0 = bo[c], bias1 = bo[c + 8];
            size_t off0 = ((size_t)b * CC + c) * NN + n;
            size_t off1 = ((size_t)b * CC + c + 8) * NN + n;
            float2 x0 = *(const float2*)&x[off0];
            float2 x1 = *(const float2*)&x[off1];
            float2 r0 = {acc[nt][0] + x0.x + bias0, acc[nt][1] + x0.y + bias0};
            float2 r1 = {acc[nt][2] + x1.x + bias1, acc[nt][3] + x1.y + bias1};
            *(float2*)&out[off0] = r0;
            *(float2*)&out[off1] = r1;
        }
    }
}

// ---------------------------------------------------------------------------
extern "C" void kernel_launch(void* const* d_in, const int* in_sizes, int n_in,
                              void* d_out, int out_size)
{
    const float* x  = (const float*)d_in[0];
    const float* wt = (const float*)d_in[1];
    const float* bt = (const float*)d_in[2];
    const float* wp = (const float*)d_in[3];
    const float* bp = (const float*)d_in[4];
    const float* wg = (const float*)d_in[5];
    const float* bg = (const float*)d_in[6];
    const float* wo = (const float*)d_in[7];
    const float* bo = (const float*)d_in[8];
    float* out = (float*)d_out;

    cudaFuncSetAttribute(proj3_tc, cudaFuncAttributeMaxDynamicSharedMemorySize, PROJ_SMEM_BYTES);
    cudaFuncSetAttribute(attn_tc,  cudaFuncAttributeMaxDynamicSharedMemorySize, ATTN_SMEM_BYTES);
    cudaFuncSetAttribute(out_tc,   cudaFuncAttributeMaxDynamicSharedMemorySize, OUT_SMEM_BYTES);

    proj3_tc<<<dim3(NN / 128, BB), 512, PROJ_SMEM_BYTES>>>(x, wt, bt, wp, bp, wg, bg);
    pool_kernel<<<(BB * MM * 32) / 256, 256>>>();
    attn_tc<<<dim3(NN / 128, BB), 256, ATTN_SMEM_BYTES>>>();
    out_tc<<<dim3(NN / 64, BB), 256, OUT_SMEM_BYTES>>>(x, wo, bo, out);
}